// round 2
// baseline (speedup 1.0000x reference)
#include <cuda_runtime.h>
#include <cstdint>

#define BB 64
#define NN 512
#define HH 128
#define NCOG 72
#define NRB 72

// Scratch (allocation-free: __device__ globals). g_w holds UNMASKED relu values
// for rows with mask_i==1; rows/cols with mask 0 are skipped by compaction, so
// their (zero-initialized, never-written) contents are never consumed.
__device__ float    g_w[(size_t)BB * NN * NN];   // 64 MB
__device__ int      g_jlist[BB][NN];             // compacted active indices per batch
__device__ int      g_jcnt[BB];
__device__ unsigned g_maxbits;                   // global max as uint bits (vals >= 0)

// ---------------------------------------------------------------------------
// K_zero: zero the output (inactive rows are never written by the GEMM).
// ---------------------------------------------------------------------------
__global__ void k_zero_out(float4* __restrict__ out, int n4) {
    int idx = blockIdx.x * blockDim.x + threadIdx.x;
    int stride = gridDim.x * blockDim.x;
    float4 z = make_float4(0.f, 0.f, 0.f, 0.f);
    for (int i = idx; i < n4; i += stride) out[i] = z;
}

// ---------------------------------------------------------------------------
// K_compact: per batch, build list of active indices (mask[b,:] != 0).
// Also resets the global max.
// ---------------------------------------------------------------------------
__global__ void k_compact(const float* __restrict__ mask) {
    int b = blockIdx.x;
    int j = threadIdx.x;          // 0..511
    if (b == 0 && j == 0) g_maxbits = 0u;

    bool act = (mask[b * NN + j] != 0.0f);
    unsigned ball = __ballot_sync(0xffffffffu, act);

    __shared__ int wcnt[16], wbase[16];
    int warp = j >> 5, lane = j & 31;
    if (lane == 0) wcnt[warp] = __popc(ball);
    __syncthreads();
    if (j == 0) {
        int s = 0;
        for (int w = 0; w < 16; w++) { wbase[w] = s; s += wcnt[w]; }
        g_jcnt[b] = s;
    }
    __syncthreads();
    if (act) {
        int pos = wbase[warp] + __popc(ball & ((1u << lane) - 1u));
        g_jlist[b][pos] = j;
    }
}

// ---------------------------------------------------------------------------
// K_build_w: for active rows i, compute w_raw[j] = relu(domain[cog,r] - d),
// store full row (coalesced), and fold masked values into the global max.
// One block per (i, b); 128 threads x 4 elems (float4/int4 vector loads).
// ---------------------------------------------------------------------------
__global__ void __launch_bounds__(128) k_build_w(
    const int*   __restrict__ rmat,
    const float* __restrict__ dmat,
    const float* __restrict__ mask,
    const int*   __restrict__ cog,
    const float* __restrict__ domain)
{
    int i = blockIdx.x, b = blockIdx.y;
    float mi = mask[b * NN + i];
    if (mi == 0.0f) return;   // dead row: never read, never written, contributes 0 to max

    size_t base = ((size_t)(b * NN + i)) * NN;
    int t  = threadIdx.x;
    int j0 = t * 4;

    int4   rv = *(const int4*)(rmat + base + j0);
    int4   cv = *(const int4*)(cog  + base + j0);
    float4 dv = *(const float4*)(dmat + base + j0);
    float4 mj = *(const float4*)(mask + (size_t)b * NN + j0);

    float w0 = fmaxf(__ldg(domain + cv.x * NRB + rv.x) - dv.x, 0.f);
    float w1 = fmaxf(__ldg(domain + cv.y * NRB + rv.y) - dv.y, 0.f);
    float w2 = fmaxf(__ldg(domain + cv.z * NRB + rv.z) - dv.z, 0.f);
    float w3 = fmaxf(__ldg(domain + cv.w * NRB + rv.w) - dv.w, 0.f);

    *(float4*)(g_w + base + j0) = make_float4(w0, w1, w2, w3);

    // max over masked values (mask_j in {0.0, 1.0} exactly)
    float lm = fmaxf(fmaxf(w0 * mj.x, w1 * mj.y), fmaxf(w2 * mj.z, w3 * mj.w));
    #pragma unroll
    for (int off = 16; off; off >>= 1)
        lm = fmaxf(lm, __shfl_xor_sync(0xffffffffu, lm, off));

    __shared__ float smax[4];
    if ((t & 31) == 0) smax[t >> 5] = lm;
    __syncthreads();
    if (t == 0) {
        float bm = fmaxf(fmaxf(smax[0], smax[1]), fmaxf(smax[2], smax[3]));
        atomicMax(&g_maxbits, __float_as_uint(bm));
    }
}

// ---------------------------------------------------------------------------
// K_gemm: compacted batched GEMM.
//   out[b, ilist[ip], h] = inv_max * sum_{kc} w[b, ilist[ip], jlist[kc]] * h_t[jlist[kc], b, h]
// Block = (i-tile of 64 compacted rows) x (all 128 h) for one batch b.
// 256 threads: tx (0..31) covers h in float4, ty (0..7) covers 8 i-rows each.
// ---------------------------------------------------------------------------
__global__ void __launch_bounds__(256) k_gemm(
    const float* __restrict__ h_t,
    float*       __restrict__ out)
{
    int b   = blockIdx.y;
    int cnt = g_jcnt[b];
    int ip0 = blockIdx.x * 64;          // offset into compacted i list
    if (ip0 >= cnt) return;             // no active rows for this block

    int tid = threadIdx.x;
    int tx  = tid & 31;                 // h quad index
    int ty  = tid >> 5;                 // i sub-group

    __shared__ float sW[64][32];        // [ii][kk]
    __shared__ float sH[32][128];       // [kk][h]
    __shared__ int   sj[32];
    __shared__ int   si[64];

    if (tid < 64) {
        int ip = ip0 + tid;
        si[tid] = (ip < cnt) ? g_jlist[b][ip] : -1;
    }

    float acc[8][4];
    #pragma unroll
    for (int a = 0; a < 8; a++)
        #pragma unroll
        for (int c = 0; c < 4; c++) acc[a][c] = 0.f;

    const float* hb = h_t + (size_t)b * HH;   // h_t[j,b,h] = hb[j*BB*HH + h]

    for (int kc0 = 0; kc0 < cnt; kc0 += 32) {
        __syncthreads();   // protect sj/sW/sH from previous iteration's readers
        if (tid < 32) {
            int idx = kc0 + tid;
            sj[tid] = (idx < cnt) ? g_jlist[b][idx] : -1;
        }
        __syncthreads();

        // Load W tile 64x32 (rows gathered via si, cols via sj).
        // Warp layout: fixed ii, kk=0..31 -> conflict-free smem stores,
        // global reads stay within one w row (good sector locality).
        #pragma unroll
        for (int rep = 0; rep < 8; rep++) {
            int e  = rep * 256 + tid;
            int ii = e >> 5;
            int kk = e & 31;
            int j    = sj[kk];
            int irow = si[ii];
            float v = 0.f;
            if (j >= 0 && irow >= 0)
                v = g_w[((size_t)(b * NN + irow)) * NN + j];
            sW[ii][kk] = v;
        }
        // Load H tile 32x128 as float4 rows (each j-row is 512B, coalesced).
        #pragma unroll
        for (int rep = 0; rep < 4; rep++) {
            int e  = rep * 256 + tid;
            int kk = e >> 5;
            int h4 = e & 31;
            int j = sj[kk];
            if (j < 0) j = 0;                         // safe addr; sW==0 kills it
            float4 hv = *(const float4*)(hb + (size_t)j * BB * HH + h4 * 4);
            *(float4*)(&sH[kk][h4 * 4]) = hv;
        }
        __syncthreads();

        #pragma unroll
        for (int kk = 0; kk < 32; kk++) {
            float4 hv = *(const float4*)(&sH[kk][tx * 4]);
            #pragma unroll
            for (int a = 0; a < 8; a++) {
                float wv = sW[ty * 8 + a][kk];        // warp-broadcast LDS
                acc[a][0] = fmaf(wv, hv.x, acc[a][0]);
                acc[a][1] = fmaf(wv, hv.y, acc[a][1]);
                acc[a][2] = fmaf(wv, hv.z, acc[a][2]);
                acc[a][3] = fmaf(wv, hv.w, acc[a][3]);
            }
        }
    }

    float inv = 1.0f / __uint_as_float(g_maxbits);
    #pragma unroll
    for (int a = 0; a < 8; a++) {
        int ip = ip0 + ty * 8 + a;
        if (ip < cnt) {
            int i = si[ty * 8 + a];
            float4 o = make_float4(acc[a][0] * inv, acc[a][1] * inv,
                                   acc[a][2] * inv, acc[a][3] * inv);
            *(float4*)(out + ((size_t)(b * NN + i)) * HH + tx * 4) = o;
        }
    }
}

// ---------------------------------------------------------------------------
extern "C" void kernel_launch(void* const* d_in, const int* in_sizes, int n_in,
                              void* d_out, int out_size)
{
    const float* h_t    = (const float*)d_in[0];   // [N,B,H]
    const int*   r_mat  = (const int*)  d_in[1];   // [B,N,N]
    const float* d_mat  = (const float*)d_in[2];   // [B,N,N]
    const float* mask   = (const float*)d_in[3];   // [B,N]
    const int*   cog    = (const int*)  d_in[4];   // [B,N,N]
    const float* domain = (const float*)d_in[5];   // [72,72]
    float* out = (float*)d_out;                    // [B,N,H]

    // 1. zero output (poisoned to 0xAA; inactive rows never written by GEMM)
    k_zero_out<<<1024, 256>>>((float4*)out, out_size / 4);
    // 2. per-batch active-index compaction + reset global max
    k_compact<<<BB, NN>>>(mask);
    // 3. gather/relu for active rows + global masked max
    dim3 g1(NN, BB);
    k_build_w<<<g1, 128>>>(r_mat, d_mat, mask, cog, domain);
    // 4. compacted batched GEMM with 1/max folded into epilogue
    dim3 g2(NN / 64, BB);
    k_gemm<<<g2, 256>>>(h_t, out);
}